// round 2
// baseline (speedup 1.0000x reference)
#include <cuda_runtime.h>
#include <cuda_bf16.h>
#include <math.h>

// ---------------- problem constants ----------------
constexpr int Bsz  = 8;
constexpr int T    = 4096;
constexpr int Hh   = 8;
constexpr int Eh   = 64;    // per-head dim
constexpr int EMB  = 512;
constexpr int Mrf  = 32;    // random features
constexpr int HID  = 2048;
constexpr int NTOK = Bsz * T;        // 32768
constexpr int NTH  = NTOK * Hh;      // 262144 token-heads
constexpr int NCH  = 16;             // T-chunks for kptv reduction
constexpr float EPS = 1e-5f;
constexpr float INV_SQRT_M = 0.17677669529663687f; // 1/sqrt(32)

// ---------------- scratch layout (floats) ----------------
constexpr size_t OFF_H      = 0;                         // [NTOK,512] ln1 out (== [NTH,64])
constexpr size_t OFF_KQV    = OFF_H      + (size_t)NTOK*EMB;        // [NTH,192] k|q|v
constexpr size_t OFF_KP     = OFF_KQV    + (size_t)NTH*192;         // [NTH,32]
constexpr size_t OFF_QP     = OFF_KP     + (size_t)NTH*32;          // [NTH,32]
constexpr size_t OFF_WRT    = OFF_QP     + (size_t)NTH*32;          // [64,32] w transposed
constexpr size_t OFF_KPTV_P = OFF_WRT    + 2048;                    // [64,16,2048]
constexpr size_t OFF_KSUM_P = OFF_KPTV_P + (size_t)64*NCH*2048;     // [64,16,32]
constexpr size_t OFF_KPTVT  = OFF_KSUM_P + (size_t)64*NCH*32;       // [64][m*64+e]
constexpr size_t OFF_KSUM   = OFF_KPTVT  + (size_t)64*2048;         // [64,32]
constexpr size_t OFF_Y      = OFF_KSUM   + 2048;                    // [NTOK,512]
constexpr size_t OFF_X2     = OFF_Y      + (size_t)NTOK*EMB;        // [NTOK,512]
constexpr size_t OFF_H2     = OFF_X2     + (size_t)NTOK*EMB;        // [NTOK,512]
constexpr size_t OFF_HID    = OFF_H2     + (size_t)NTOK*EMB;        // [NTOK,2048]
constexpr size_t SCR_TOTAL  = OFF_HID    + (size_t)NTOK*HID;        // ~204M floats

__device__ float g_scr[SCR_TOTAL];

// ---------------- LayerNorm (one block per token) ----------------
__global__ void __launch_bounds__(256)
k_layernorm(const float* __restrict__ x, const float* __restrict__ g,
            const float* __restrict__ b, float* __restrict__ out)
{
    int tok = blockIdx.x, tid = threadIdx.x;
    const float* xr = x + (size_t)tok * EMB;
    float v0 = xr[tid], v1 = xr[tid + 256];
    float s = v0 + v1, sq = v0 * v0 + v1 * v1;
    __shared__ float red[2][8];
    #pragma unroll
    for (int o = 16; o; o >>= 1) {
        s  += __shfl_xor_sync(0xffffffffu, s,  o);
        sq += __shfl_xor_sync(0xffffffffu, sq, o);
    }
    if ((tid & 31) == 0) { red[0][tid >> 5] = s; red[1][tid >> 5] = sq; }
    __syncthreads();
    if (tid < 32) {
        float a = (tid < 8) ? red[0][tid] : 0.f;
        float c = (tid < 8) ? red[1][tid] : 0.f;
        #pragma unroll
        for (int o = 4; o; o >>= 1) {
            a += __shfl_xor_sync(0xffffffffu, a, o);
            c += __shfl_xor_sync(0xffffffffu, c, o);
        }
        if (tid == 0) { red[0][0] = a; red[1][0] = c; }
    }
    __syncthreads();
    float mu  = red[0][0] * (1.f / EMB);
    float var = red[1][0] * (1.f / EMB) - mu * mu;
    float r   = rsqrtf(var + EPS);
    out[(size_t)tok * EMB + tid]       = (v0 - mu) * r * g[tid]       + b[tid];
    out[(size_t)tok * EMB + tid + 256] = (v1 - mu) * r * g[tid + 256] + b[tid + 256];
}

// ---------------- generic SGEMM: C[r,n] = sum_k A[r,k]*W[n,k] + epi ----------------
// EPI: 0 = +bias ; 1 = gelu(.+bias) ; 2 = +bias+res
template<int EPI>
__global__ void __launch_bounds__(256)
k_sgemm(const float* __restrict__ A, const float* __restrict__ W,
        const float* __restrict__ bias, const float* __restrict__ res,
        float* __restrict__ C, int N, int K)
{
    __shared__ float As[8][128];
    __shared__ float Bs[8][128];
    const int tid  = threadIdx.x;
    const int bm   = blockIdx.x * 128, bn = blockIdx.y * 128;
    const int lrow = tid >> 1;
    const int lseg = (tid & 1) * 4;
    const float* Ap = A + (size_t)(bm + lrow) * K + lseg;
    const int    wn = bn + lrow;
    const float* Wp = W + (size_t)wn * K + lseg;
    const bool wv = (wn < N);
    const int ty = tid >> 4, tx = tid & 15;

    float acc[8][8];
    #pragma unroll
    for (int i = 0; i < 8; i++)
        #pragma unroll
        for (int j = 0; j < 8; j++) acc[i][j] = 0.f;

    float4 a4 = *(const float4*)(Ap);
    float4 b4 = wv ? *(const float4*)(Wp) : make_float4(0.f, 0.f, 0.f, 0.f);

    for (int k0 = 0; k0 < K; k0 += 8) {
        __syncthreads();
        As[lseg + 0][lrow] = a4.x; As[lseg + 1][lrow] = a4.y;
        As[lseg + 2][lrow] = a4.z; As[lseg + 3][lrow] = a4.w;
        Bs[lseg + 0][lrow] = b4.x; Bs[lseg + 1][lrow] = b4.y;
        Bs[lseg + 2][lrow] = b4.z; Bs[lseg + 3][lrow] = b4.w;
        __syncthreads();
        if (k0 + 8 < K) {
            a4 = *(const float4*)(Ap + k0 + 8);
            b4 = wv ? *(const float4*)(Wp + k0 + 8) : make_float4(0.f, 0.f, 0.f, 0.f);
        }
        #pragma unroll
        for (int kk = 0; kk < 8; kk++) {
            float a[8], bb[8];
            *(float4*)(a)      = *(const float4*)&As[kk][ty * 8];
            *(float4*)(a + 4)  = *(const float4*)&As[kk][ty * 8 + 4];
            *(float4*)(bb)     = *(const float4*)&Bs[kk][tx * 8];
            *(float4*)(bb + 4) = *(const float4*)&Bs[kk][tx * 8 + 4];
            #pragma unroll
            for (int i = 0; i < 8; i++)
                #pragma unroll
                for (int j = 0; j < 8; j++)
                    acc[i][j] += a[i] * bb[j];
        }
    }
    #pragma unroll
    for (int i = 0; i < 8; i++) {
        int r = bm + ty * 8 + i;
        #pragma unroll
        for (int j = 0; j < 8; j++) {
            int c = bn + tx * 8 + j;
            if (c < N) {
                float v = acc[i][j] + bias[c];
                if (EPI == 1) v = 0.5f * v * (1.f + erff(v * 0.70710678118654752f));
                if (EPI == 2) v += res[(size_t)r * N + c];
                C[(size_t)r * N + c] = v;
            }
        }
    }
}

// ---------------- transpose random-feature matrix once ----------------
__global__ void k_wrT(const float* __restrict__ w, float* __restrict__ wrT)
{
    int i = threadIdx.x + blockIdx.x * 256;
    if (i < 2048) { int e = i >> 5, m = i & 31; wrT[e * 32 + m] = w[m * 64 + e]; }
}

// ---------------- prm_exp for k and q (64 token-heads per block) ----------------
__global__ void __launch_bounds__(256)
k_prm(const float* __restrict__ kqv, const float* __restrict__ wrT,
      float* __restrict__ kp, float* __restrict__ qp)
{
    __shared__ float zs[64][65];
    __shared__ float ws[64][32];
    int tid = threadIdx.x;
    int th0 = blockIdx.x * 64;
    for (int i = tid; i < 2048; i += 256) ws[i >> 5][i & 31] = wrT[i];
    int w = tid >> 5, lane = tid & 31;
    int thb = w * 8;

    for (int kq = 0; kq < 2; kq++) {
        __syncthreads();
        for (int i = tid; i < 4096; i += 256) {
            int th = i >> 6, e = i & 63;
            zs[th][e] = kqv[(size_t)(th0 + th) * 192 + kq * 64 + e];
        }
        __syncthreads();
        float* out = kq ? qp : kp;
        float acc[8], xd[8];
        #pragma unroll
        for (int i = 0; i < 8; i++) {
            float z0 = zs[thb + i][lane], z1 = zs[thb + i][lane + 32];
            float p = z0 * z0 + z1 * z1;
            #pragma unroll
            for (int o = 16; o; o >>= 1) p += __shfl_xor_sync(0xffffffffu, p, o);
            xd[i] = 0.5f * p;
            acc[i] = 0.f;
        }
        #pragma unroll 4
        for (int e = 0; e < 64; e++) {
            float wvv = ws[e][lane];
            #pragma unroll
            for (int i = 0; i < 8; i++) acc[i] += zs[thb + i][e] * wvv;
        }
        #pragma unroll
        for (int i = 0; i < 8; i++)
            out[(size_t)(th0 + thb + i) * 32 + lane] = __expf(acc[i] - xd[i]) * INV_SQRT_M;
    }
}

// ---------------- kptv / ksum partial reduction over T chunks ----------------
__global__ void __launch_bounds__(256)
k_kptv_part(const float* __restrict__ kp, const float* __restrict__ kqv,
            float* __restrict__ kptv_p, float* __restrict__ ksum_p)
{
    int bh = blockIdx.x >> 4;
    int ch = blockIdx.x & 15;
    int b  = bh >> 3, h = bh & 7;
    int tid = threadIdx.x, eg = tid >> 5, lane = tid & 31;
    __shared__ float ks[8][32];
    __shared__ float vs[8][64];
    float acc[8] = {0, 0, 0, 0, 0, 0, 0, 0};
    float ksacc = 0.f;
    int tbase = ch * (T / NCH);
    for (int tt = 0; tt < T / NCH; tt += 8) {
        __syncthreads();
        {
            int tb = tid >> 5, m = tid & 31;
            int t = tbase + tt + tb;
            ks[tb][m] = kp[((size_t)((b * T + t) * Hh + h)) * 32 + m];
        }
        #pragma unroll
        for (int i = tid; i < 512; i += 256) {
            int tb = i >> 6, e = i & 63;
            int t = tbase + tt + tb;
            vs[tb][e] = kqv[(size_t)((b * T + t) * Hh + h) * 192 + 128 + e];
        }
        __syncthreads();
        #pragma unroll
        for (int tb = 0; tb < 8; tb++) {
            float kv = ks[tb][lane];
            if (eg == 0) ksacc += kv;
            #pragma unroll
            for (int j = 0; j < 8; j++) acc[j] += vs[tb][eg * 8 + j] * kv;
        }
    }
    size_t base = (size_t)blockIdx.x * 2048;
    #pragma unroll
    for (int j = 0; j < 8; j++) kptv_p[base + (eg * 8 + j) * 32 + lane] = acc[j];
    if (tid < 32) ksum_p[blockIdx.x * 32 + tid] = ksacc;
}

__global__ void __launch_bounds__(256)
k_kptv_red(const float* __restrict__ p, const float* __restrict__ ksp,
           float* __restrict__ kptvT, float* __restrict__ ksum)
{
    int bh = blockIdx.x, tid = threadIdx.x;
    for (int i = tid; i < 2048; i += 256) {
        float s = 0.f;
        #pragma unroll
        for (int c = 0; c < NCH; c++) s += p[((size_t)bh * NCH + c) * 2048 + i];
        int e = i >> 5, m = i & 31;
        kptvT[(size_t)bh * 2048 + m * 64 + e] = s;  // transposed [m][e]
    }
    if (tid < 32) {
        float s = 0.f;
        #pragma unroll
        for (int c = 0; c < NCH; c++) s += ksp[(bh * NCH + c) * 32 + tid];
        ksum[bh * 32 + tid] = s;
    }
}

// ---------------- y = (qp @ kptv^T) / D   (32 tokens x 2 heads per block) ----------------
__global__ void __launch_bounds__(256)
k_y(const float* __restrict__ qp, const float* __restrict__ kptvT,
    const float* __restrict__ ksum, float* __restrict__ y)
{
    __shared__ float kpt[2][2048];
    __shared__ float qps[64][33];
    __shared__ float kss[2][32];
    __shared__ float Ds[64];
    int tid = threadIdx.x;
    int hp = blockIdx.x & 3, h0 = hp * 2;
    int tok0 = (blockIdx.x >> 2) * 32;
    int b = tok0 >> 12;
    size_t kbase = (size_t)(b * 8 + h0) * 2048;
    for (int i = tid; i < 4096; i += 256) kpt[i >> 11][i & 2047] = kptvT[kbase + i];
    if (tid < 64) kss[tid >> 5][tid & 31] = ksum[(b * 8 + h0) * 32 + tid];
    for (int j = tid; j < 2048; j += 256) {
        int t = j >> 6, r = j & 63, hh = r >> 5, m = r & 31;
        qps[t * 2 + hh][m] = qp[(size_t)(tok0 + t) * 256 + (h0 + hh) * 32 + m];
    }
    __syncthreads();
    if (tid < 64) {
        int t = tid >> 1, hh = tid & 1;
        float s = 0.f;
        #pragma unroll
        for (int m = 0; m < 32; m++) s += qps[t * 2 + hh][m] * kss[hh][m];
        Ds[tid] = s;
    }
    __syncthreads();
    int w = tid >> 5, lane = tid & 31;
    int hh = w & 1, gg = w >> 1;
    float a0[8] = {0,0,0,0,0,0,0,0}, a1[8] = {0,0,0,0,0,0,0,0};
    #pragma unroll 4
    for (int m = 0; m < 32; m++) {
        float k0 = kpt[hh][m * 64 + lane];
        float k1 = kpt[hh][m * 64 + lane + 32];
        #pragma unroll
        for (int t = 0; t < 8; t++) {
            float qv = qps[(gg * 8 + t) * 2 + hh][m];
            a0[t] += qv * k0; a1[t] += qv * k1;
        }
    }
    #pragma unroll
    for (int t = 0; t < 8; t++) {
        int tok = tok0 + gg * 8 + t;
        float inv = 1.0f / Ds[(gg * 8 + t) * 2 + hh];
        y[(size_t)tok * 512 + (h0 + hh) * 64 + lane]      = a0[t] * inv;
        y[(size_t)tok * 512 + (h0 + hh) * 64 + lane + 32] = a1[t] * inv;
    }
}

// ---------------- launcher ----------------
extern "C" void kernel_launch(void* const* d_in, const int* in_sizes, int n_in,
                              void* d_out, int out_size)
{
    (void)in_sizes; (void)n_in; (void)out_size;
    const float* x      = (const float*)d_in[0];
    const float* w_rf   = (const float*)d_in[1];
    const float* kqv_w  = (const float*)d_in[2];
    const float* kqv_b  = (const float*)d_in[3];
    const float* proj_w = (const float*)d_in[4];
    const float* proj_b = (const float*)d_in[5];
    const float* ln1_g  = (const float*)d_in[6];
    const float* ln1_b  = (const float*)d_in[7];
    const float* ln2_g  = (const float*)d_in[8];
    const float* ln2_b  = (const float*)d_in[9];
    const float* w1     = (const float*)d_in[10];
    const float* b1     = (const float*)d_in[11];
    const float* w2     = (const float*)d_in[12];
    const float* b2     = (const float*)d_in[13];
    float* out = (float*)d_out;

    float* scr = nullptr;
    cudaGetSymbolAddress((void**)&scr, g_scr);
    float* dh     = scr + OFF_H;
    float* dkqv   = scr + OFF_KQV;
    float* dkp    = scr + OFF_KP;
    float* dqp    = scr + OFF_QP;
    float* dwrT   = scr + OFF_WRT;
    float* dkptvp = scr + OFF_KPTV_P;
    float* dksump = scr + OFF_KSUM_P;
    float* dkptvT = scr + OFF_KPTVT;
    float* dksum  = scr + OFF_KSUM;
    float* dy     = scr + OFF_Y;
    float* dx2    = scr + OFF_X2;
    float* dh2    = scr + OFF_H2;
    float* dhid   = scr + OFF_HID;

    // 1. LN1
    k_layernorm<<<NTOK, 256>>>(x, ln1_g, ln1_b, dh);
    // 2. kqv = h @ kqv_w^T + b  ([262144,64] x [192,64]^T)
    k_sgemm<0><<<dim3(NTH / 128, 2), 256>>>(dh, kqv_w, kqv_b, nullptr, dkqv, 192, 64);
    // 3. random features
    k_wrT<<<8, 256>>>(w_rf, dwrT);
    k_prm<<<NTH / 64, 256>>>(dkqv, dwrT, dkp, dqp);
    // 4. kptv / ksum reduction over T
    k_kptv_part<<<64 * NCH, 256>>>(dkp, dkqv, dkptvp, dksump);
    k_kptv_red<<<64, 256>>>(dkptvp, dksump, dkptvT, dksum);
    // 5. y
    k_y<<<(NTOK / 32) * 4, 256>>>(dqp, dkptvT, dksum, dy);
    // 6. attn proj + residual -> x2
    k_sgemm<2><<<dim3(NTOK / 128, 4), 256>>>(dy, proj_w, proj_b, x, dx2, 512, 512);
    // 7. LN2
    k_layernorm<<<NTOK, 256>>>(dx2, ln2_g, ln2_b, dh2);
    // 8. MLP
    k_sgemm<1><<<dim3(NTOK / 128, 16), 256>>>(dh2, w1, b1, nullptr, dhid, 2048, 512);
    k_sgemm<2><<<dim3(NTOK / 128, 4), 256>>>(dhid, w2, b2, dx2, out, 512, 2048);
}

// round 3
// speedup vs baseline: 2.4773x; 2.4773x over previous
#include <cuda_runtime.h>
#include <cuda_bf16.h>
#include <math.h>
#include <stdint.h>

// ---------------- problem constants ----------------
constexpr int Bsz  = 8;
constexpr int T    = 4096;
constexpr int Hh   = 8;
constexpr int EMB  = 512;
constexpr int HID  = 2048;
constexpr int NTOK = Bsz * T;        // 32768
constexpr int NTH  = NTOK * Hh;      // 262144 token-heads
constexpr int NCH  = 16;             // T-chunks for kptv reduction
constexpr float EPS = 1e-5f;
constexpr float INV_SQRT_M = 0.17677669529663687f; // 1/sqrt(32)

// ---------------- scratch layout (floats) ----------------
constexpr size_t OFF_H      = 0;
constexpr size_t OFF_KQV    = OFF_H      + (size_t)NTOK*EMB;
constexpr size_t OFF_KP     = OFF_KQV    + (size_t)NTH*192;
constexpr size_t OFF_QP     = OFF_KP     + (size_t)NTH*32;
constexpr size_t OFF_WRT    = OFF_QP     + (size_t)NTH*32;
constexpr size_t OFF_KPTV_P = OFF_WRT    + 2048;
constexpr size_t OFF_KSUM_P = OFF_KPTV_P + (size_t)64*NCH*2048;
constexpr size_t OFF_KPTVT  = OFF_KSUM_P + (size_t)64*NCH*32;
constexpr size_t OFF_KSUM   = OFF_KPTVT  + (size_t)64*2048;
constexpr size_t OFF_Y      = OFF_KSUM   + 2048;
constexpr size_t OFF_X2     = OFF_Y      + (size_t)NTOK*EMB;
constexpr size_t OFF_H2     = OFF_X2     + (size_t)NTOK*EMB;
constexpr size_t OFF_HID    = OFF_H2     + (size_t)NTOK*EMB;
constexpr size_t SCR_TOTAL  = OFF_HID    + (size_t)NTOK*HID;

__device__ float g_scr[SCR_TOTAL];

// ---------------- helpers ----------------
__device__ __forceinline__ float to_tf32(float x) {
    float r; asm("cvt.rna.tf32.f32 %0, %1;" : "=f"(r) : "f"(x)); return r;
}
__device__ __forceinline__ float4 t4(float4 v) {
    return make_float4(to_tf32(v.x), to_tf32(v.y), to_tf32(v.z), to_tf32(v.w));
}
__device__ __forceinline__ void mma_tf32(float* d, const uint32_t* a,
                                         uint32_t b0, uint32_t b1) {
    asm volatile(
        "mma.sync.aligned.m16n8k8.row.col.f32.tf32.tf32.f32 "
        "{%0,%1,%2,%3}, {%4,%5,%6,%7}, {%8,%9}, {%0,%1,%2,%3};\n"
        : "+f"(d[0]), "+f"(d[1]), "+f"(d[2]), "+f"(d[3])
        : "r"(a[0]), "r"(a[1]), "r"(a[2]), "r"(a[3]), "r"(b0), "r"(b1));
}

// ---------------- LayerNorm (one block per token) ----------------
__global__ void __launch_bounds__(256)
k_layernorm(const float* __restrict__ x, const float* __restrict__ g,
            const float* __restrict__ b, float* __restrict__ out)
{
    int tok = blockIdx.x, tid = threadIdx.x;
    const float* xr = x + (size_t)tok * EMB;
    float v0 = xr[tid], v1 = xr[tid + 256];
    float s = v0 + v1, sq = v0 * v0 + v1 * v1;
    __shared__ float red[2][8];
    #pragma unroll
    for (int o = 16; o; o >>= 1) {
        s  += __shfl_xor_sync(0xffffffffu, s,  o);
        sq += __shfl_xor_sync(0xffffffffu, sq, o);
    }
    if ((tid & 31) == 0) { red[0][tid >> 5] = s; red[1][tid >> 5] = sq; }
    __syncthreads();
    if (tid < 32) {
        float a = (tid < 8) ? red[0][tid] : 0.f;
        float c = (tid < 8) ? red[1][tid] : 0.f;
        #pragma unroll
        for (int o = 4; o; o >>= 1) {
            a += __shfl_xor_sync(0xffffffffu, a, o);
            c += __shfl_xor_sync(0xffffffffu, c, o);
        }
        if (tid == 0) { red[0][0] = a; red[1][0] = c; }
    }
    __syncthreads();
    float mu  = red[0][0] * (1.f / EMB);
    float var = red[1][0] * (1.f / EMB) - mu * mu;
    float r   = rsqrtf(var + EPS);
    out[(size_t)tok * EMB + tid]       = (v0 - mu) * r * g[tid]       + b[tid];
    out[(size_t)tok * EMB + tid + 256] = (v1 - mu) * r * g[tid + 256] + b[tid + 256];
}

// ---------------- fp32 SGEMM (used for kqv only; K=64, N=192) ----------------
template<int EPI>
__global__ void __launch_bounds__(256)
k_sgemm(const float* __restrict__ A, const float* __restrict__ W,
        const float* __restrict__ bias, const float* __restrict__ res,
        float* __restrict__ C, int N, int K)
{
    __shared__ float As[8][128];
    __shared__ float Bs[8][128];
    const int tid  = threadIdx.x;
    const int bm   = blockIdx.x * 128, bn = blockIdx.y * 128;
    const int lrow = tid >> 1;
    const int lseg = (tid & 1) * 4;
    const float* Ap = A + (size_t)(bm + lrow) * K + lseg;
    const int    wn = bn + lrow;
    const float* Wp = W + (size_t)wn * K + lseg;
    const bool wv = (wn < N);
    const int ty = tid >> 4, tx = tid & 15;

    float acc[8][8];
    #pragma unroll
    for (int i = 0; i < 8; i++)
        #pragma unroll
        for (int j = 0; j < 8; j++) acc[i][j] = 0.f;

    float4 a4 = *(const float4*)(Ap);
    float4 b4 = wv ? *(const float4*)(Wp) : make_float4(0.f, 0.f, 0.f, 0.f);

    for (int k0 = 0; k0 < K; k0 += 8) {
        __syncthreads();
        As[lseg + 0][lrow] = a4.x; As[lseg + 1][lrow] = a4.y;
        As[lseg + 2][lrow] = a4.z; As[lseg + 3][lrow] = a4.w;
        Bs[lseg + 0][lrow] = b4.x; Bs[lseg + 1][lrow] = b4.y;
        Bs[lseg + 2][lrow] = b4.z; Bs[lseg + 3][lrow] = b4.w;
        __syncthreads();
        if (k0 + 8 < K) {
            a4 = *(const float4*)(Ap + k0 + 8);
            b4 = wv ? *(const float4*)(Wp + k0 + 8) : make_float4(0.f, 0.f, 0.f, 0.f);
        }
        #pragma unroll
        for (int kk = 0; kk < 8; kk++) {
            float a[8], bb[8];
            *(float4*)(a)      = *(const float4*)&As[kk][ty * 8];
            *(float4*)(a + 4)  = *(const float4*)&As[kk][ty * 8 + 4];
            *(float4*)(bb)     = *(const float4*)&Bs[kk][tx * 8];
            *(float4*)(bb + 4) = *(const float4*)&Bs[kk][tx * 8 + 4];
            #pragma unroll
            for (int i = 0; i < 8; i++)
                #pragma unroll
                for (int j = 0; j < 8; j++)
                    acc[i][j] += a[i] * bb[j];
        }
    }
    #pragma unroll
    for (int i = 0; i < 8; i++) {
        int r = bm + ty * 8 + i;
        #pragma unroll
        for (int j = 0; j < 8; j++) {
            int c = bn + tx * 8 + j;
            if (c < N) {
                float v = acc[i][j] + bias[c];
                if (EPI == 1) v = 0.5f * v * (1.f + erff(v * 0.70710678118654752f));
                if (EPI == 2) v += res[(size_t)r * N + c];
                C[(size_t)r * N + c] = v;
            }
        }
    }
}

// ---------------- tf32 tensor-core GEMM: C = A[M,K] @ W[N,K]^T (+epi) ----------------
// Requires M % 128 == 0, N % 128 == 0, K % 16 == 0.
// EPI: 0 = +bias ; 1 = gelu(.+bias) ; 2 = +bias+res
template<int EPI>
__global__ void __launch_bounds__(256, 2)
k_tf32gemm(const float* __restrict__ A, const float* __restrict__ W,
           const float* __restrict__ bias, const float* __restrict__ res,
           float* __restrict__ C, int N, int K)
{
    constexpr int LDT = 20;                  // 16 + 4 pad (conflict-free fragment loads)
    __shared__ float As[128 * LDT];
    __shared__ float Bs[128 * LDT];
    const int tid  = threadIdx.x;
    const int bm   = blockIdx.x * 128, bn = blockIdx.y * 128;
    const int warp = tid >> 5, lane = tid & 31;
    const int wm   = (warp & 3) * 32;        // 4 warps along M
    const int wn   = (warp >> 2) * 64;       // 2 warps along N
    const int gid  = lane >> 2, tig = lane & 3;

    const int lr = tid >> 2;                 // 0..63 (load row)
    const int lc = (tid & 3) * 4;            // 0,4,8,12 (load col)
    const float* Ap0 = A + (size_t)(bm + lr)      * K + lc;
    const float* Ap1 = A + (size_t)(bm + lr + 64) * K + lc;
    const float* Wp0 = W + (size_t)(bn + lr)      * K + lc;
    const float* Wp1 = W + (size_t)(bn + lr + 64) * K + lc;

    float acc[2][8][4];
    #pragma unroll
    for (int mi = 0; mi < 2; mi++)
        #pragma unroll
        for (int nj = 0; nj < 8; nj++)
            #pragma unroll
            for (int q = 0; q < 4; q++) acc[mi][nj][q] = 0.f;

    float4 pa0 = *(const float4*)Ap0;
    float4 pa1 = *(const float4*)Ap1;
    float4 pb0 = *(const float4*)Wp0;
    float4 pb1 = *(const float4*)Wp1;

    for (int k0 = 0; k0 < K; k0 += 16) {
        __syncthreads();
        *(float4*)&As[lr * LDT + lc]        = t4(pa0);
        *(float4*)&As[(lr + 64) * LDT + lc] = t4(pa1);
        *(float4*)&Bs[lr * LDT + lc]        = t4(pb0);
        *(float4*)&Bs[(lr + 64) * LDT + lc] = t4(pb1);
        __syncthreads();
        if (k0 + 16 < K) {
            pa0 = *(const float4*)(Ap0 + k0 + 16);
            pa1 = *(const float4*)(Ap1 + k0 + 16);
            pb0 = *(const float4*)(Wp0 + k0 + 16);
            pb1 = *(const float4*)(Wp1 + k0 + 16);
        }
        #pragma unroll
        for (int kk = 0; kk < 16; kk += 8) {
            uint32_t af[2][4];
            #pragma unroll
            for (int mi = 0; mi < 2; mi++) {
                int rb = (wm + mi * 16 + gid) * LDT + kk + tig;
                af[mi][0] = __float_as_uint(As[rb]);
                af[mi][1] = __float_as_uint(As[rb + 8 * LDT]);
                af[mi][2] = __float_as_uint(As[rb + 4]);
                af[mi][3] = __float_as_uint(As[rb + 8 * LDT + 4]);
            }
            #pragma unroll
            for (int nj = 0; nj < 8; nj++) {
                int cb = (wn + nj * 8 + gid) * LDT + kk + tig;
                uint32_t bf0 = __float_as_uint(Bs[cb]);
                uint32_t bf1 = __float_as_uint(Bs[cb + 4]);
                mma_tf32(acc[0][nj], af[0], bf0, bf1);
                mma_tf32(acc[1][nj], af[1], bf0, bf1);
            }
        }
    }

    // epilogue
    #pragma unroll
    for (int mi = 0; mi < 2; mi++) {
        int rr = bm + wm + mi * 16 + gid;
        #pragma unroll
        for (int nj = 0; nj < 8; nj++) {
            int cc = bn + wn + nj * 8 + tig * 2;
            float bs0 = bias[cc], bs1 = bias[cc + 1];
            float v0 = acc[mi][nj][0] + bs0;
            float v1 = acc[mi][nj][1] + bs1;
            float v2 = acc[mi][nj][2] + bs0;
            float v3 = acc[mi][nj][3] + bs1;
            if (EPI == 1) {
                v0 = 0.5f * v0 * (1.f + erff(v0 * 0.70710678118654752f));
                v1 = 0.5f * v1 * (1.f + erff(v1 * 0.70710678118654752f));
                v2 = 0.5f * v2 * (1.f + erff(v2 * 0.70710678118654752f));
                v3 = 0.5f * v3 * (1.f + erff(v3 * 0.70710678118654752f));
            }
            if (EPI == 2) {
                const float* r0 = res + (size_t)rr * N + cc;
                const float* r1 = res + (size_t)(rr + 8) * N + cc;
                v0 += r0[0]; v1 += r0[1];
                v2 += r1[0]; v3 += r1[1];
            }
            *(float2*)(C + (size_t)rr * N + cc)       = make_float2(v0, v1);
            *(float2*)(C + (size_t)(rr + 8) * N + cc) = make_float2(v2, v3);
        }
    }
}

// ---------------- transpose random-feature matrix once ----------------
__global__ void k_wrT(const float* __restrict__ w, float* __restrict__ wrT)
{
    int i = threadIdx.x + blockIdx.x * 256;
    if (i < 2048) { int e = i >> 5, m = i & 31; wrT[e * 32 + m] = w[m * 64 + e]; }
}

// ---------------- prm_exp for k and q (64 token-heads per block) ----------------
__global__ void __launch_bounds__(256)
k_prm(const float* __restrict__ kqv, const float* __restrict__ wrT,
      float* __restrict__ kp, float* __restrict__ qp)
{
    __shared__ float zs[64][65];
    __shared__ float ws[64][32];
    int tid = threadIdx.x;
    int th0 = blockIdx.x * 64;
    for (int i = tid; i < 2048; i += 256) ws[i >> 5][i & 31] = wrT[i];
    int w = tid >> 5, lane = tid & 31;
    int thb = w * 8;

    for (int kq = 0; kq < 2; kq++) {
        __syncthreads();
        for (int i = tid; i < 4096; i += 256) {
            int th = i >> 6, e = i & 63;
            zs[th][e] = kqv[(size_t)(th0 + th) * 192 + kq * 64 + e];
        }
        __syncthreads();
        float* out = kq ? qp : kp;
        float acc[8], xd[8];
        #pragma unroll
        for (int i = 0; i < 8; i++) {
            float z0 = zs[thb + i][lane], z1 = zs[thb + i][lane + 32];
            float p = z0 * z0 + z1 * z1;
            #pragma unroll
            for (int o = 16; o; o >>= 1) p += __shfl_xor_sync(0xffffffffu, p, o);
            xd[i] = 0.5f * p;
            acc[i] = 0.f;
        }
        #pragma unroll 4
        for (int e = 0; e < 64; e++) {
            float wvv = ws[e][lane];
            #pragma unroll
            for (int i = 0; i < 8; i++) acc[i] += zs[thb + i][e] * wvv;
        }
        #pragma unroll
        for (int i = 0; i < 8; i++)
            out[(size_t)(th0 + thb + i) * 32 + lane] = __expf(acc[i] - xd[i]) * INV_SQRT_M;
    }
}

// ---------------- kptv / ksum partial reduction over T chunks ----------------
__global__ void __launch_bounds__(256)
k_kptv_part(const float* __restrict__ kp, const float* __restrict__ kqv,
            float* __restrict__ kptv_p, float* __restrict__ ksum_p)
{
    int bh = blockIdx.x >> 4;
    int ch = blockIdx.x & 15;
    int b  = bh >> 3, h = bh & 7;
    int tid = threadIdx.x, eg = tid >> 5, lane = tid & 31;
    __shared__ float ks[8][32];
    __shared__ float vs[8][64];
    float acc[8] = {0, 0, 0, 0, 0, 0, 0, 0};
    float ksacc = 0.f;
    int tbase = ch * (T / NCH);
    for (int tt = 0; tt < T / NCH; tt += 8) {
        __syncthreads();
        {
            int tb = tid >> 5, m = tid & 31;
            int t = tbase + tt + tb;
            ks[tb][m] = kp[((size_t)((b * T + t) * Hh + h)) * 32 + m];
        }
        #pragma unroll
        for (int i = tid; i < 512; i += 256) {
            int tb = i >> 6, e = i & 63;
            int t = tbase + tt + tb;
            vs[tb][e] = kqv[(size_t)((b * T + t) * Hh + h) * 192 + 128 + e];
        }
        __syncthreads();
        #pragma unroll
        for (int tb = 0; tb < 8; tb++) {
            float kv = ks[tb][lane];
            if (eg == 0) ksacc += kv;
            #pragma unroll
            for (int j = 0; j < 8; j++) acc[j] += vs[tb][eg * 8 + j] * kv;
        }
    }
    size_t base = (size_t)blockIdx.x * 2048;
    #pragma unroll
    for (int j = 0; j < 8; j++) kptv_p[base + (eg * 8 + j) * 32 + lane] = acc[j];
    if (tid < 32) ksum_p[blockIdx.x * 32 + tid] = ksacc;
}

__global__ void __launch_bounds__(256)
k_kptv_red(const float* __restrict__ p, const float* __restrict__ ksp,
           float* __restrict__ kptvT, float* __restrict__ ksum)
{
    int bh = blockIdx.x, tid = threadIdx.x;
    for (int i = tid; i < 2048; i += 256) {
        float s = 0.f;
        #pragma unroll
        for (int c = 0; c < NCH; c++) s += p[((size_t)bh * NCH + c) * 2048 + i];
        int e = i >> 5, m = i & 31;
        kptvT[(size_t)bh * 2048 + m * 64 + e] = s;  // transposed [m][e]
    }
    if (tid < 32) {
        float s = 0.f;
        #pragma unroll
        for (int c = 0; c < NCH; c++) s += ksp[(bh * NCH + c) * 32 + tid];
        ksum[bh * 32 + tid] = s;
    }
}

// ---------------- y = (qp @ kptv^T) / D   (32 tokens x 2 heads per block) ----------------
__global__ void __launch_bounds__(256)
k_y(const float* __restrict__ qp, const float* __restrict__ kptvT,
    const float* __restrict__ ksum, float* __restrict__ y)
{
    __shared__ float kpt[2][2048];
    __shared__ float qps[64][33];
    __shared__ float kss[2][32];
    __shared__ float Ds[64];
    int tid = threadIdx.x;
    int hp = blockIdx.x & 3, h0 = hp * 2;
    int tok0 = (blockIdx.x >> 2) * 32;
    int b = tok0 >> 12;
    size_t kbase = (size_t)(b * 8 + h0) * 2048;
    for (int i = tid; i < 4096; i += 256) kpt[i >> 11][i & 2047] = kptvT[kbase + i];
    if (tid < 64) kss[tid >> 5][tid & 31] = ksum[(b * 8 + h0) * 32 + tid];
    for (int j = tid; j < 2048; j += 256) {
        int t = j >> 6, r = j & 63, hh = r >> 5, m = r & 31;
        qps[t * 2 + hh][m] = qp[(size_t)(tok0 + t) * 256 + (h0 + hh) * 32 + m];
    }
    __syncthreads();
    if (tid < 64) {
        int t = tid >> 1, hh = tid & 1;
        float s = 0.f;
        #pragma unroll
        for (int m = 0; m < 32; m++) s += qps[t * 2 + hh][m] * kss[hh][m];
        Ds[tid] = s;
    }
    __syncthreads();
    int w = tid >> 5, lane = tid & 31;
    int hh = w & 1, gg = w >> 1;
    float a0[8] = {0,0,0,0,0,0,0,0}, a1[8] = {0,0,0,0,0,0,0,0};
    #pragma unroll 4
    for (int m = 0; m < 32; m++) {
        float k0 = kpt[hh][m * 64 + lane];
        float k1 = kpt[hh][m * 64 + lane + 32];
        #pragma unroll
        for (int t = 0; t < 8; t++) {
            float qv = qps[(gg * 8 + t) * 2 + hh][m];
            a0[t] += qv * k0; a1[t] += qv * k1;
        }
    }
    #pragma unroll
    for (int t = 0; t < 8; t++) {
        int tok = tok0 + gg * 8 + t;
        float inv = 1.0f / Ds[(gg * 8 + t) * 2 + hh];
        y[(size_t)tok * 512 + (h0 + hh) * 64 + lane]      = a0[t] * inv;
        y[(size_t)tok * 512 + (h0 + hh) * 64 + lane + 32] = a1[t] * inv;
    }
}

// ---------------- launcher ----------------
extern "C" void kernel_launch(void* const* d_in, const int* in_sizes, int n_in,
                              void* d_out, int out_size)
{
    (void)in_sizes; (void)n_in; (void)out_size;
    const float* x      = (const float*)d_in[0];
    const float* w_rf   = (const float*)d_in[1];
    const float* kqv_w  = (const float*)d_in[2];
    const float* kqv_b  = (const float*)d_in[3];
    const float* proj_w = (const float*)d_in[4];
    const float* proj_b = (const float*)d_in[5];
    const float* ln1_g  = (const float*)d_in[6];
    const float* ln1_b  = (const float*)d_in[7];
    const float* ln2_g  = (const float*)d_in[8];
    const float* ln2_b  = (const float*)d_in[9];
    const float* w1     = (const float*)d_in[10];
    const float* b1     = (const float*)d_in[11];
    const float* w2     = (const float*)d_in[12];
    const float* b2     = (const float*)d_in[13];
    float* out = (float*)d_out;

    float* scr = nullptr;
    cudaGetSymbolAddress((void**)&scr, g_scr);
    float* dh     = scr + OFF_H;
    float* dkqv   = scr + OFF_KQV;
    float* dkp    = scr + OFF_KP;
    float* dqp    = scr + OFF_QP;
    float* dwrT   = scr + OFF_WRT;
    float* dkptvp = scr + OFF_KPTV_P;
    float* dksump = scr + OFF_KSUM_P;
    float* dkptvT = scr + OFF_KPTVT;
    float* dksum  = scr + OFF_KSUM;
    float* dy     = scr + OFF_Y;
    float* dx2    = scr + OFF_X2;
    float* dh2    = scr + OFF_H2;
    float* dhid   = scr + OFF_HID;

    // 1. LN1
    k_layernorm<<<NTOK, 256>>>(x, ln1_g, ln1_b, dh);
    // 2. kqv = h @ kqv_w^T + b (fp32 — feeds exp(), keep full precision)
    k_sgemm<0><<<dim3(NTH / 128, 2), 256>>>(dh, kqv_w, kqv_b, nullptr, dkqv, 192, 64);
    // 3. random features
    k_wrT<<<8, 256>>>(w_rf, dwrT);
    k_prm<<<NTH / 64, 256>>>(dkqv, dwrT, dkp, dqp);
    // 4. kptv / ksum reduction over T
    k_kptv_part<<<64 * NCH, 256>>>(dkp, dkqv, dkptvp, dksump);
    k_kptv_red<<<64, 256>>>(dkptvp, dksump, dkptvT, dksum);
    // 5. y
    k_y<<<(NTOK / 32) * 4, 256>>>(dqp, dkptvT, dksum, dy);
    // 6. attn proj + residual -> x2 (tf32 tensor cores)
    k_tf32gemm<2><<<dim3(NTOK / 128, 4), 256>>>(dy, proj_w, proj_b, x, dx2, 512, 512);
    // 7. LN2
    k_layernorm<<<NTOK, 256>>>(dx2, ln2_g, ln2_b, dh2);
    // 8. MLP (tf32 tensor cores)
    k_tf32gemm<1><<<dim3(NTOK / 128, 16), 256>>>(dh2, w1, b1, nullptr, dhid, 2048, 512);
    k_tf32gemm<2><<<dim3(NTOK / 128, 4), 256>>>(dhid, w2, b2, dx2, out, 512, 2048);
}

// round 12
// speedup vs baseline: 3.9135x; 1.5798x over previous
#include <cuda_runtime.h>
#include <cuda_fp16.h>
#include <math.h>
#include <stdint.h>

// ---------------- problem constants ----------------
constexpr int Bsz  = 8;
constexpr int T    = 4096;
constexpr int Hh   = 8;
constexpr int EMB  = 512;
constexpr int HID  = 2048;
constexpr int NTOK = Bsz * T;        // 32768
constexpr int NTH  = NTOK * Hh;      // 262144 token-heads
constexpr int NCH  = 16;             // T-chunks for kptv reduction
constexpr float EPS = 1e-5f;
constexpr float INV_SQRT_M = 0.17677669529663687f; // 1/sqrt(32)

// ---------------- scratch layout (float units) ----------------
constexpr size_t OFF_H      = 0;                                  // [NTOK,512] fp32 (LN1)
constexpr size_t OFF_KQV    = OFF_H      + (size_t)NTOK*EMB;      // [NTH,192] fp32
constexpr size_t OFF_KP     = OFF_KQV    + (size_t)NTH*192;
constexpr size_t OFF_QP     = OFF_KP     + (size_t)NTH*32;
constexpr size_t OFF_WRT    = OFF_QP     + (size_t)NTH*32;
constexpr size_t OFF_KPTV_P = OFF_WRT    + 2048;
constexpr size_t OFF_KSUM_P = OFF_KPTV_P + (size_t)64*NCH*2048;
constexpr size_t OFF_KPTVT  = OFF_KSUM_P + (size_t)64*NCH*32;
constexpr size_t OFF_KSUM   = OFF_KPTVT  + (size_t)64*2048;
constexpr size_t OFF_X2     = OFF_KSUM   + 2048;                  // [NTOK,512] fp32
constexpr size_t OFF_YH     = OFF_X2     + (size_t)NTOK*EMB;      // [NTOK,512] half
constexpr size_t OFF_H2H    = OFF_YH     + (size_t)NTOK*EMB/2;    // [NTOK,512] half
constexpr size_t OFF_HIDH   = OFF_H2H    + (size_t)NTOK*EMB/2;    // [NTOK,2048] half
constexpr size_t OFF_PWH    = OFF_HIDH   + (size_t)NTOK*HID/2;    // 512*512 half
constexpr size_t OFF_W1H    = OFF_PWH    + (size_t)512*512/2;     // 2048*512 half
constexpr size_t OFF_W2H    = OFF_W1H    + (size_t)2048*512/2;    // 512*2048 half
constexpr size_t SCR_TOTAL  = OFF_W2H    + (size_t)512*2048/2;

__device__ float g_scr[SCR_TOTAL];

// ---------------- helpers ----------------
__device__ __forceinline__ void st_out(float* p, float v)  { *p = v; }
__device__ __forceinline__ void st_out(__half* p, float v) { *p = __float2half_rn(v); }

__device__ __forceinline__ void mma_f16(float* d, const uint32_t* a,
                                        uint32_t b0, uint32_t b1) {
    asm volatile(
        "mma.sync.aligned.m16n8k16.row.col.f32.f16.f16.f32 "
        "{%0,%1,%2,%3}, {%4,%5,%6,%7}, {%8,%9}, {%0,%1,%2,%3};\n"
        : "+f"(d[0]), "+f"(d[1]), "+f"(d[2]), "+f"(d[3])
        : "r"(a[0]), "r"(a[1]), "r"(a[2]), "r"(a[3]), "r"(b0), "r"(b1));
}
__device__ __forceinline__ uint32_t smem_u32(const void* p) {
    uint32_t a;
    asm("{ .reg .u64 t; cvta.to.shared.u64 t, %1; cvt.u32.u64 %0, t; }" : "=r"(a) : "l"(p));
    return a;
}
__device__ __forceinline__ void cp16(uint32_t dst, const void* src) {
    asm volatile("cp.async.ca.shared.global [%0], [%1], 16;" :: "r"(dst), "l"(src));
}

// ---------------- float -> half conversion (weights) ----------------
__global__ void __launch_bounds__(256)
k_f2h(const float* __restrict__ in, __half* __restrict__ out)
{
    int i = (blockIdx.x * 256 + threadIdx.x) * 4;
    float4 v = *(const float4*)(in + i);
    *(__half2*)(out + i)     = __floats2half2_rn(v.x, v.y);
    *(__half2*)(out + i + 2) = __floats2half2_rn(v.z, v.w);
}

// ---------------- LayerNorm (one block per token), templated output ----------------
template<typename OT>
__global__ void __launch_bounds__(256)
k_layernorm(const float* __restrict__ x, const float* __restrict__ g,
            const float* __restrict__ b, OT* __restrict__ out)
{
    int tok = blockIdx.x, tid = threadIdx.x;
    const float* xr = x + (size_t)tok * EMB;
    float v0 = xr[tid], v1 = xr[tid + 256];
    float s = v0 + v1, sq = v0 * v0 + v1 * v1;
    __shared__ float red[2][8];
    #pragma unroll
    for (int o = 16; o; o >>= 1) {
        s  += __shfl_xor_sync(0xffffffffu, s,  o);
        sq += __shfl_xor_sync(0xffffffffu, sq, o);
    }
    if ((tid & 31) == 0) { red[0][tid >> 5] = s; red[1][tid >> 5] = sq; }
    __syncthreads();
    if (tid < 32) {
        float a = (tid < 8) ? red[0][tid] : 0.f;
        float c = (tid < 8) ? red[1][tid] : 0.f;
        #pragma unroll
        for (int o = 4; o; o >>= 1) {
            a += __shfl_xor_sync(0xffffffffu, a, o);
            c += __shfl_xor_sync(0xffffffffu, c, o);
        }
        if (tid == 0) { red[0][0] = a; red[1][0] = c; }
    }
    __syncthreads();
    float mu  = red[0][0] * (1.f / EMB);
    float var = red[1][0] * (1.f / EMB) - mu * mu;
    float r   = rsqrtf(var + EPS);
    st_out(out + (size_t)tok * EMB + tid,       (v0 - mu) * r * g[tid]       + b[tid]);
    st_out(out + (size_t)tok * EMB + tid + 256, (v1 - mu) * r * g[tid + 256] + b[tid + 256]);
}

// ---------------- fp32 SGEMM (kqv only; K=64, N=192 — feeds exp) ----------------
template<int EPI>
__global__ void __launch_bounds__(256)
k_sgemm(const float* __restrict__ A, const float* __restrict__ W,
        const float* __restrict__ bias, const float* __restrict__ res,
        float* __restrict__ C, int N, int K)
{
    __shared__ float As[8][128];
    __shared__ float Bs[8][128];
    const int tid  = threadIdx.x;
    const int bm   = blockIdx.x * 128, bn = blockIdx.y * 128;
    const int lrow = tid >> 1;
    const int lseg = (tid & 1) * 4;
    const float* Ap = A + (size_t)(bm + lrow) * K + lseg;
    const int    wn = bn + lrow;
    const float* Wp = W + (size_t)wn * K + lseg;
    const bool wv = (wn < N);
    const int ty = tid >> 4, tx = tid & 15;

    float acc[8][8];
    #pragma unroll
    for (int i = 0; i < 8; i++)
        #pragma unroll
        for (int j = 0; j < 8; j++) acc[i][j] = 0.f;

    float4 a4 = *(const float4*)(Ap);
    float4 b4 = wv ? *(const float4*)(Wp) : make_float4(0.f, 0.f, 0.f, 0.f);

    for (int k0 = 0; k0 < K; k0 += 8) {
        __syncthreads();
        As[lseg + 0][lrow] = a4.x; As[lseg + 1][lrow] = a4.y;
        As[lseg + 2][lrow] = a4.z; As[lseg + 3][lrow] = a4.w;
        Bs[lseg + 0][lrow] = b4.x; Bs[lseg + 1][lrow] = b4.y;
        Bs[lseg + 2][lrow] = b4.z; Bs[lseg + 3][lrow] = b4.w;
        __syncthreads();
        if (k0 + 8 < K) {
            a4 = *(const float4*)(Ap + k0 + 8);
            b4 = wv ? *(const float4*)(Wp + k0 + 8) : make_float4(0.f, 0.f, 0.f, 0.f);
        }
        #pragma unroll
        for (int kk = 0; kk < 8; kk++) {
            float a[8], bb[8];
            *(float4*)(a)      = *(const float4*)&As[kk][ty * 8];
            *(float4*)(a + 4)  = *(const float4*)&As[kk][ty * 8 + 4];
            *(float4*)(bb)     = *(const float4*)&Bs[kk][tx * 8];
            *(float4*)(bb + 4) = *(const float4*)&Bs[kk][tx * 8 + 4];
            #pragma unroll
            for (int i = 0; i < 8; i++)
                #pragma unroll
                for (int j = 0; j < 8; j++)
                    acc[i][j] += a[i] * bb[j];
        }
    }
    #pragma unroll
    for (int i = 0; i < 8; i++) {
        int r = bm + ty * 8 + i;
        #pragma unroll
        for (int j = 0; j < 8; j++) {
            int c = bn + tx * 8 + j;
            if (c < N) C[(size_t)r * N + c] = acc[i][j] + bias[c];
        }
    }
}

// ---------------- fp16 tensor-core GEMM: C = A[M,K]h @ W[N,K]h^T (+epi) ----------------
// CTA 128x128, 4 warps of 64x64. BK=64 halves. cp.async double-buffered.
// smem row stride 144B (72 halves = 36 words, ≡4 mod 32 → conflict-free frags).
// EPI: 1 = gelu(.+bias) ; 2 = +bias+res
constexpr int HG_BUF  = 128 * 144 * 2;      // A-tile + B-tile per stage (36864B)
constexpr int HG_SMEM = 2 * HG_BUF;         // 73728B
template<int EPI, typename OT>
__global__ void __launch_bounds__(128, 2)
k_hgemm(const __half* __restrict__ A, const __half* __restrict__ W,
        const float* __restrict__ bias, const float* __restrict__ res,
        OT* __restrict__ C, int N, int K)
{
    extern __shared__ char sm[];
    const int tid  = threadIdx.x;
    const int bn   = blockIdx.x * 128, bm = blockIdx.y * 128;
    const int warp = tid >> 5, lane = tid & 31;
    const int wm   = (warp & 1) * 64;
    const int wn   = (warp >> 1) * 64;
    const int gid  = lane >> 2, tig = lane & 3;
    const uint32_t sbase = smem_u32(sm);

    float acc[4][8][4];
    #pragma unroll
    for (int mi = 0; mi < 4; mi++)
        #pragma unroll
        for (int nj = 0; nj < 8; nj++)
            #pragma unroll
            for (int q = 0; q < 4; q++) acc[mi][nj][q] = 0.f;

    auto prefetch = [&](int c) {
        const int k0 = c * 64;
        const uint32_t buf = sbase + (c & 1) * HG_BUF;
        #pragma unroll
        for (int i = 0; i < 8; i++) {
            int idx = tid + 128 * i;          // 0..1023
            int row = idx >> 3, seg = idx & 7;
            cp16(buf + row * 144 + seg * 16,
                 A + (size_t)(bm + row) * K + k0 + seg * 8);
            cp16(buf + 128 * 144 + row * 144 + seg * 16,
                 W + (size_t)(bn + row) * K + k0 + seg * 8);
        }
        asm volatile("cp.async.commit_group;" ::: "memory");
    };

    const int nch = K >> 6;
    prefetch(0);
    for (int c = 0; c < nch; c++) {
        if (c + 1 < nch) {
            prefetch(c + 1);
            asm volatile("cp.async.wait_group 1;" ::: "memory");
        } else {
            asm volatile("cp.async.wait_group 0;" ::: "memory");
        }
        __syncthreads();
        const char* As = sm + (c & 1) * HG_BUF;
        const char* Bs = As + 128 * 144;
        #pragma unroll
        for (int kk = 0; kk < 4; kk++) {
            uint32_t af[4][4];
            #pragma unroll
            for (int mi = 0; mi < 4; mi++) {
                const char* r0 = As + (wm + mi * 16 + gid) * 144 + (kk * 8 + tig) * 4;
                af[mi][0] = *(const uint32_t*)(r0);
                af[mi][1] = *(const uint32_t*)(r0 + 8 * 144);
                af[mi][2] = *(const uint32_t*)(r0 + 16);
                af[mi][3] = *(const uint32_t*)(r0 + 8 * 144 + 16);
            }
            #pragma unroll
            for (int nj = 0; nj < 8; nj++) {
                const char* rb = Bs + (wn + nj * 8 + gid) * 144 + (kk * 8 + tig) * 4;
                uint32_t b0 = *(const uint32_t*)(rb);
                uint32_t b1 = *(const uint32_t*)(rb + 16);
                #pragma unroll
                for (int mi = 0; mi < 4; mi++)
                    mma_f16(acc[mi][nj], af[mi], b0, b1);
            }
        }
        __syncthreads();
    }

    // epilogue: thread owns rows (r0, r0+8), cols (cc, cc+1) per (mi,nj)
    #pragma unroll
    for (int mi = 0; mi < 4; mi++) {
        const int r0 = bm + wm + mi * 16 + gid;
        #pragma unroll
        for (int nj = 0; nj < 8; nj++) {
            const int cc = bn + wn + nj * 8 + tig * 2;
            const float bs0 = bias[cc], bs1 = bias[cc + 1];
            float v0 = acc[mi][nj][0] + bs0;
            float v1 = acc[mi][nj][1] + bs1;
            float v2 = acc[mi][nj][2] + bs0;
            float v3 = acc[mi][nj][3] + bs1;
            if (EPI == 1) {
                v0 = 0.5f * v0 * (1.f + erff(v0 * 0.70710678118654752f));
                v1 = 0.5f * v1 * (1.f + erff(v1 * 0.70710678118654752f));
                v2 = 0.5f * v2 * (1.f + erff(v2 * 0.70710678118654752f));
                v3 = 0.5f * v3 * (1.f + erff(v3 * 0.70710678118654752f));
            }
            if (EPI == 2) {
                float2 ra = *(const float2*)(res + (size_t)r0 * N + cc);
                float2 rb = *(const float2*)(res + (size_t)(r0 + 8) * N + cc);
                v0 += ra.x; v1 += ra.y; v2 += rb.x; v3 += rb.y;
            }
            st_out(C + (size_t)r0 * N + cc,           v0);
            st_out(C + (size_t)r0 * N + cc + 1,       v1);
            st_out(C + (size_t)(r0 + 8) * N + cc,     v2);
            st_out(C + (size_t)(r0 + 8) * N + cc + 1, v3);
        }
    }
}

// ---------------- transpose random-feature matrix once ----------------
__global__ void k_wrT(const float* __restrict__ w, float* __restrict__ wrT)
{
    int i = threadIdx.x + blockIdx.x * 256;
    if (i < 2048) { int e = i >> 5, m = i & 31; wrT[e * 32 + m] = w[m * 64 + e]; }
}

// ---------------- prm_exp for k and q (64 token-heads per block) ----------------
__global__ void __launch_bounds__(256)
k_prm(const float* __restrict__ kqv, const float* __restrict__ wrT,
      float* __restrict__ kp, float* __restrict__ qp)
{
    __shared__ float zs[64][65];
    __shared__ float ws[64][32];
    int tid = threadIdx.x;
    int th0 = blockIdx.x * 64;
    for (int i = tid; i < 2048; i += 256) ws[i >> 5][i & 31] = wrT[i];
    int w = tid >> 5, lane = tid & 31;
    int thb = w * 8;

    for (int kq = 0; kq < 2; kq++) {
        __syncthreads();
        for (int i = tid; i < 4096; i += 256) {
            int th = i >> 6, e = i & 63;
            zs[th][e] = kqv[(size_t)(th0 + th) * 192 + kq * 64 + e];
        }
        __syncthreads();
        float* out = kq ? qp : kp;
        float acc[8], xd[8];
        #pragma unroll
        for (int i = 0; i < 8; i++) {
            float z0 = zs[thb + i][lane], z1 = zs[thb + i][lane + 32];
            float p = z0 * z0 + z1 * z1;
            #pragma unroll
            for (int o = 16; o; o >>= 1) p += __shfl_xor_sync(0xffffffffu, p, o);
            xd[i] = 0.5f * p;
            acc[i] = 0.f;
        }
        #pragma unroll 4
        for (int e = 0; e < 64; e++) {
            float wvv = ws[e][lane];
            #pragma unroll
            for (int i = 0; i < 8; i++) acc[i] += zs[thb + i][e] * wvv;
        }
        #pragma unroll
        for (int i = 0; i < 8; i++)
            out[(size_t)(th0 + thb + i) * 32 + lane] = __expf(acc[i] - xd[i]) * INV_SQRT_M;
    }
}

// ---------------- kptv / ksum partial reduction over T chunks ----------------
__global__ void __launch_bounds__(256)
k_kptv_part(const float* __restrict__ kp, const float* __restrict__ kqv,
            float* __restrict__ kptv_p, float* __restrict__ ksum_p)
{
    int bh = blockIdx.x >> 4;
    int ch = blockIdx.x & 15;
    int b  = bh >> 3, h = bh & 7;
    int tid = threadIdx.x, eg = tid >> 5, lane = tid & 31;
    __shared__ float ks[8][32];
    __shared__ float vs[8][64];
    float acc[8] = {0, 0, 0, 0, 0, 0, 0, 0};
    float ksacc = 0.f;
    int tbase = ch * (T / NCH);
    for (int tt = 0; tt < T / NCH; tt += 8) {
        __syncthreads();
        {
            int tb = tid >> 5, m = tid & 31;
            int t = tbase + tt + tb;
            ks[tb][m] = kp[((size_t)((b * T + t) * Hh + h)) * 32 + m];
        }
        #pragma unroll
        for (int i = tid; i < 512; i += 256) {
            int tb = i >> 6, e = i & 63;
            int t = tbase + tt + tb;
            vs[tb][e] = kqv[(size_t)((b * T + t) * Hh + h) * 192 + 128 + e];
        }
        __syncthreads();
        #pragma unroll
        for (int tb = 0; tb < 8; tb++) {
            float kv = ks[tb][lane];
            if (eg == 0) ksacc += kv;
            #pragma unroll
            for (int j = 0; j < 8; j++) acc[j] += vs[tb][eg * 8 + j] * kv;
        }
    }
    size_t base = (size_t)blockIdx.x * 2048;
    #pragma unroll
    for (int j = 0; j < 8; j++) kptv_p[base + (eg * 8 + j) * 32 + lane] = acc[j];
    if (tid < 32) ksum_p[blockIdx.x * 32 + tid] = ksacc;
}

__global__ void __launch_bounds__(256)
k_kptv_red(const float* __restrict__ p, const float* __restrict__ ksp,
           float* __restrict__ kptvT, float* __restrict__ ksum)
{
    int bh = blockIdx.x, tid = threadIdx.x;
    for (int i = tid; i < 2048; i += 256) {
        float s = 0.f;
        #pragma unroll
        for (int c = 0; c < NCH; c++) s += p[((size_t)bh * NCH + c) * 2048 + i];
        int e = i >> 5, m = i & 31;
        kptvT[(size_t)bh * 2048 + m * 64 + e] = s;  // transposed [m][e]
    }
    if (tid < 32) {
        float s = 0.f;
        #pragma unroll
        for (int c = 0; c < NCH; c++) s += ksp[(bh * NCH + c) * 32 + tid];
        ksum[bh * 32 + tid] = s;
    }
}

// ---------------- y = (qp @ kptv^T) / D   (32 tokens x 2 heads per block; half out) ----
__global__ void __launch_bounds__(256)
k_y(const float* __restrict__ qp, const float* __restrict__ kptvT,
    const float* __restrict__ ksum, __half* __restrict__ y)
{
    __shared__ float kpt[2][2048];
    __shared__ float qps[64][33];
    __shared__ float kss[2][32];
    __shared__ float Ds[64];
    int tid = threadIdx.x;
    int hp = blockIdx.x & 3, h0 = hp * 2;
    int tok0 = (blockIdx.x >> 2) * 32;
    int b = tok0 >> 12;
    size_t kbase = (size_t)(b * 8 + h0) * 2048;
    for (int i = tid; i < 4096; i += 256) kpt[i >> 11][i & 2047] = kptvT[kbase + i];
    if (tid < 64) kss[tid >> 5][tid & 31] = ksum[(b * 8 + h0) * 32 + tid];
    for (int j = tid; j < 2048; j += 256) {
        int t = j >> 6, r = j & 63, hh = r >> 5, m = r & 31;
        qps[t * 2 + hh][m] = qp[(size_t)(tok0 + t) * 256 + (h0 + hh) * 32 + m];
    }
    __syncthreads();
    if (tid < 64) {
        int t = tid >> 1, hh = tid & 1;
        float s = 0.f;
        #pragma unroll
        for (int m = 0; m < 32; m++) s += qps[t * 2 + hh][m] * kss[hh][m];
        Ds[tid] = s;
    }
    __syncthreads();
    int w = tid >> 5, lane = tid & 31;
    int hh = w & 1, gg = w >> 1;
    float a0[8] = {0,0,0,0,0,0,0,0}, a1[8] = {0,0,0,0,0,0,0,0};
    #pragma unroll 4
    for (int m = 0; m < 32; m++) {
        float k0 = kpt[hh][m * 64 + lane];
        float k1 = kpt[hh][m * 64 + lane + 32];
        #pragma unroll
        for (int t = 0; t < 8; t++) {
            float qv = qps[(gg * 8 + t) * 2 + hh][m];
            a0[t] += qv * k0; a1[t] += qv * k1;
        }
    }
    #pragma unroll
    for (int t = 0; t < 8; t++) {
        int tok = tok0 + gg * 8 + t;
        float inv = 1.0f / Ds[(gg * 8 + t) * 2 + hh];
        y[(size_t)tok * 512 + (h0 + hh) * 64 + lane]      = __float2half_rn(a0[t] * inv);
        y[(size_t)tok * 512 + (h0 + hh) * 64 + lane + 32] = __float2half_rn(a1[t] * inv);
    }
}

// ---------------- launcher ----------------
extern "C" void kernel_launch(void* const* d_in, const int* in_sizes, int n_in,
                              void* d_out, int out_size)
{
    (void)in_sizes; (void)n_in; (void)out_size;
    const float* x      = (const float*)d_in[0];
    const float* w_rf   = (const float*)d_in[1];
    const float* kqv_w  = (const float*)d_in[2];
    const float* kqv_b  = (const float*)d_in[3];
    const float* proj_w = (const float*)d_in[4];
    const float* proj_b = (const float*)d_in[5];
    const float* ln1_g  = (const float*)d_in[6];
    const float* ln1_b  = (const float*)d_in[7];
    const float* ln2_g  = (const float*)d_in[8];
    const float* ln2_b  = (const float*)d_in[9];
    const float* w1     = (const float*)d_in[10];
    const float* b1     = (const float*)d_in[11];
    const float* w2     = (const float*)d_in[12];
    const float* b2     = (const float*)d_in[13];
    float* out = (float*)d_out;

    float* scr = nullptr;
    cudaGetSymbolAddress((void**)&scr, g_scr);
    float*  dh     = scr + OFF_H;
    float*  dkqv   = scr + OFF_KQV;
    float*  dkp    = scr + OFF_KP;
    float*  dqp    = scr + OFF_QP;
    float*  dwrT   = scr + OFF_WRT;
    float*  dkptvp = scr + OFF_KPTV_P;
    float*  dksump = scr + OFF_KSUM_P;
    float*  dkptvT = scr + OFF_KPTVT;
    float*  dksum  = scr + OFF_KSUM;
    float*  dx2    = scr + OFF_X2;
    __half* dyh    = (__half*)(scr + OFF_YH);
    __half* dh2h   = (__half*)(scr + OFF_H2H);
    __half* dhidh  = (__half*)(scr + OFF_HIDH);
    __half* dpwh   = (__half*)(scr + OFF_PWH);
    __half* dw1h   = (__half*)(scr + OFF_W1H);
    __half* dw2h   = (__half*)(scr + OFF_W2H);

    cudaFuncSetAttribute(k_hgemm<1, __half>, cudaFuncAttributeMaxDynamicSharedMemorySize, HG_SMEM);
    cudaFuncSetAttribute(k_hgemm<2, float>,  cudaFuncAttributeMaxDynamicSharedMemorySize, HG_SMEM);

    // 0. weight conversions (independent)
    k_f2h<<<512 * 512 / 1024, 256>>>(proj_w, dpwh);
    k_f2h<<<2048 * 512 / 1024, 256>>>(w1, dw1h);
    k_f2h<<<512 * 2048 / 1024, 256>>>(w2, dw2h);
    // 1. LN1 (fp32 out — feeds fp32 kqv GEMM)
    k_layernorm<float><<<NTOK, 256>>>(x, ln1_g, ln1_b, dh);
    // 2. kqv = h @ kqv_w^T + b (fp32 — feeds exp(), keep full precision)
    k_sgemm<0><<<dim3(NTH / 128, 2), 256>>>(dh, kqv_w, kqv_b, nullptr, dkqv, 192, 64);
    // 3. random features
    k_wrT<<<8, 256>>>(w_rf, dwrT);
    k_prm<<<NTH / 64, 256>>>(dkqv, dwrT, dkp, dqp);
    // 4. kptv / ksum reduction over T
    k_kptv_part<<<64 * NCH, 256>>>(dkp, dkqv, dkptvp, dksump);
    k_kptv_red<<<64, 256>>>(dkptvp, dksump, dkptvT, dksum);
    // 5. y (half out)
    k_y<<<(NTOK / 32) * 4, 256>>>(dqp, dkptvT, dksum, dyh);
    // 6. attn proj + residual -> x2 (fp16 tensor cores)
    k_hgemm<2, float><<<dim3(4, NTOK / 128), 128, HG_SMEM>>>(dyh, dpwh, proj_b, x, dx2, 512, 512);
    // 7. LN2 (half out)
    k_layernorm<__half><<<NTOK, 256>>>(dx2, ln2_g, ln2_b, dh2h);
    // 8. MLP (fp16 tensor cores)
    k_hgemm<1, __half><<<dim3(16, NTOK / 128), 128, HG_SMEM>>>(dh2h, dw1h, b1, nullptr, dhidh, 2048, 512);
    k_hgemm<2, float><<<dim3(4, NTOK / 128), 128, HG_SMEM>>>(dhidh, dw2h, b2, dx2, out, 512, 2048);
}

// round 15
// speedup vs baseline: 4.7752x; 1.2202x over previous
#include <cuda_runtime.h>
#include <cuda_fp16.h>
#include <math.h>
#include <stdint.h>

// ---------------- problem constants ----------------
constexpr int Bsz  = 8;
constexpr int T    = 4096;
constexpr int Hh   = 8;
constexpr int EMB  = 512;
constexpr int HID  = 2048;
constexpr int NTOK = Bsz * T;        // 32768
constexpr int NTH  = NTOK * Hh;      // 262144 token-heads
constexpr int NCH  = 16;             // T-chunks for kptv reduction
constexpr float EPS = 1e-5f;
constexpr float INV_SQRT_M = 0.17677669529663687f; // 1/sqrt(32)

// ---------------- scratch layout (float units) ----------------
constexpr size_t OFF_H      = 0;                                  // [NTOK,512] half (LN1 out)
constexpr size_t OFF_KQV    = OFF_H      + (size_t)NTOK*EMB;      // [NTH,192] fp32
constexpr size_t OFF_KP     = OFF_KQV    + (size_t)NTH*192;
constexpr size_t OFF_QP     = OFF_KP     + (size_t)NTH*32;
constexpr size_t OFF_WRT    = OFF_QP     + (size_t)NTH*32;
constexpr size_t OFF_KPTV_P = OFF_WRT    + 2048;
constexpr size_t OFF_KSUM_P = OFF_KPTV_P + (size_t)64*NCH*2048;
constexpr size_t OFF_KPTVT  = OFF_KSUM_P + (size_t)64*NCH*32;
constexpr size_t OFF_KSUM   = OFF_KPTVT  + (size_t)64*2048;
constexpr size_t OFF_X2     = OFF_KSUM   + 2048;                  // [NTOK,512] fp32
constexpr size_t OFF_YH     = OFF_X2     + (size_t)NTOK*EMB;      // [NTOK,512] half
constexpr size_t OFF_H2H    = OFF_YH     + (size_t)NTOK*EMB/2;    // [NTOK,512] half
constexpr size_t OFF_HIDH   = OFF_H2H    + (size_t)NTOK*EMB/2;    // [NTOK,2048] half
constexpr size_t OFF_PWH    = OFF_HIDH   + (size_t)NTOK*HID/2;    // 512*512 half
constexpr size_t OFF_W1H    = OFF_PWH    + (size_t)512*512/2;     // 2048*512 half
constexpr size_t OFF_W2H    = OFF_W1H    + (size_t)2048*512/2;    // 512*2048 half
constexpr size_t OFF_KWH    = OFF_W2H    + (size_t)512*2048/2;    // 256*64 half (padded kqv_w)
constexpr size_t SCR_TOTAL  = OFF_KWH    + (size_t)256*64/2;

__device__ float g_scr[SCR_TOTAL];

// ---------------- helpers ----------------
__device__ __forceinline__ void st_out(float* p, float v)  { *p = v; }
__device__ __forceinline__ void st_out(__half* p, float v) { *p = __float2half_rn(v); }

__device__ __forceinline__ void mma_f16(float* d, const uint32_t* a,
                                        uint32_t b0, uint32_t b1) {
    asm volatile(
        "mma.sync.aligned.m16n8k16.row.col.f32.f16.f16.f32 "
        "{%0,%1,%2,%3}, {%4,%5,%6,%7}, {%8,%9}, {%0,%1,%2,%3};\n"
        : "+f"(d[0]), "+f"(d[1]), "+f"(d[2]), "+f"(d[3])
        : "r"(a[0]), "r"(a[1]), "r"(a[2]), "r"(a[3]), "r"(b0), "r"(b1));
}
__device__ __forceinline__ void ldsm4(uint32_t* r, uint32_t addr) {
    asm volatile("ldmatrix.sync.aligned.m8n8.x4.shared.b16 {%0,%1,%2,%3}, [%4];"
        : "=r"(r[0]), "=r"(r[1]), "=r"(r[2]), "=r"(r[3]) : "r"(addr));
}
__device__ __forceinline__ uint32_t smem_u32(const void* p) {
    uint32_t a;
    asm("{ .reg .u64 t; cvta.to.shared.u64 t, %1; cvt.u32.u64 %0, t; }" : "=r"(a) : "l"(p));
    return a;
}
__device__ __forceinline__ void cp16(uint32_t dst, const void* src) {
    asm volatile("cp.async.ca.shared.global [%0], [%1], 16;" :: "r"(dst), "l"(src));
}

// ---------------- float -> half conversion (weights) ----------------
__global__ void __launch_bounds__(256)
k_f2h(const float* __restrict__ in, __half* __restrict__ out)
{
    int i = (blockIdx.x * 256 + threadIdx.x) * 4;
    float4 v = *(const float4*)(in + i);
    *(__half2*)(out + i)     = __floats2half2_rn(v.x, v.y);
    *(__half2*)(out + i + 2) = __floats2half2_rn(v.z, v.w);
}

// zero-padded variant (for kqv_w: 192*64 valid -> 256*64 total)
__global__ void __launch_bounds__(256)
k_f2h_pad(const float* __restrict__ in, __half* __restrict__ out, int nvalid, int ntotal)
{
    int i = blockIdx.x * 256 + threadIdx.x;
    if (i < ntotal) out[i] = (i < nvalid) ? __float2half_rn(in[i]) : __float2half_rn(0.f);
}

// ---------------- LayerNorm (one block per token), templated output ----------------
template<typename OT>
__global__ void __launch_bounds__(256)
k_layernorm(const float* __restrict__ x, const float* __restrict__ g,
            const float* __restrict__ b, OT* __restrict__ out)
{
    int tok = blockIdx.x, tid = threadIdx.x;
    const float* xr = x + (size_t)tok * EMB;
    float v0 = xr[tid], v1 = xr[tid + 256];
    float s = v0 + v1, sq = v0 * v0 + v1 * v1;
    __shared__ float red[2][8];
    #pragma unroll
    for (int o = 16; o; o >>= 1) {
        s  += __shfl_xor_sync(0xffffffffu, s,  o);
        sq += __shfl_xor_sync(0xffffffffu, sq, o);
    }
    if ((tid & 31) == 0) { red[0][tid >> 5] = s; red[1][tid >> 5] = sq; }
    __syncthreads();
    if (tid < 32) {
        float a = (tid < 8) ? red[0][tid] : 0.f;
        float c = (tid < 8) ? red[1][tid] : 0.f;
        #pragma unroll
        for (int o = 4; o; o >>= 1) {
            a += __shfl_xor_sync(0xffffffffu, a, o);
            c += __shfl_xor_sync(0xffffffffu, c, o);
        }
        if (tid == 0) { red[0][0] = a; red[1][0] = c; }
    }
    __syncthreads();
    float mu  = red[0][0] * (1.f / EMB);
    float var = red[1][0] * (1.f / EMB) - mu * mu;
    float r   = rsqrtf(var + EPS);
    st_out(out + (size_t)tok * EMB + tid,       (v0 - mu) * r * g[tid]       + b[tid]);
    st_out(out + (size_t)tok * EMB + tid + 256, (v1 - mu) * r * g[tid + 256] + b[tid + 256]);
}

// ---------------- fp16 tensor-core GEMM: C = A[M,K]h @ W[N,K]h^T (+epi) ----------------
// CTA 128x128, 4 warps of 64x64. BK=64 halves. cp.async double-buffered.
// smem row stride 144B (72 halves = 36 words, ≡4 mod 32 → conflict-free ldmatrix).
// Fragment loads via ldmatrix.x4 (8 per k16-step vs 32 scalar LDS).
// W must have at least gridDim.x*128 rows (pad if N not multiple of 128).
// EPI: 0 = +bias ; 1 = gelu(.+bias) ; 2 = +bias+res
constexpr int HG_BUF  = 128 * 144 * 2;      // A-tile + B-tile per stage (36864B)
constexpr int HG_SMEM = 2 * HG_BUF;         // 73728B
template<int EPI, typename OT>
__global__ void __launch_bounds__(128, 2)
k_hgemm(const __half* __restrict__ A, const __half* __restrict__ W,
        const float* __restrict__ bias, const float* __restrict__ res,
        OT* __restrict__ C, int N, int K)
{
    extern __shared__ char sm[];
    const int tid  = threadIdx.x;
    const int bn   = blockIdx.x * 128, bm = blockIdx.y * 128;
    const int warp = tid >> 5, lane = tid & 31;
    const int wm   = (warp & 1) * 64;
    const int wn   = (warp >> 1) * 64;
    const int gid  = lane >> 2, tig = lane & 3;
    const uint32_t sbase = smem_u32(sm);

    // ldmatrix lane addressing (byte offsets within a 128x144B tile)
    const uint32_t a_row = (uint32_t)(wm + (lane & 15));
    const uint32_t a_sel = (uint32_t)((lane >> 4) * 16);         // k-half select
    const uint32_t b_row = (uint32_t)(wn + ((lane >> 4) * 8) + (lane & 7));
    const uint32_t b_sel = (uint32_t)(((lane >> 3) & 1) * 16);

    float acc[4][8][4];
    #pragma unroll
    for (int mi = 0; mi < 4; mi++)
        #pragma unroll
        for (int nj = 0; nj < 8; nj++)
            #pragma unroll
            for (int q = 0; q < 4; q++) acc[mi][nj][q] = 0.f;

    auto prefetch = [&](int c) {
        const int k0 = c * 64;
        const uint32_t buf = sbase + (c & 1) * HG_BUF;
        #pragma unroll
        for (int i = 0; i < 8; i++) {
            int idx = tid + 128 * i;          // 0..1023
            int row = idx >> 3, seg = idx & 7;
            cp16(buf + row * 144 + seg * 16,
                 A + (size_t)(bm + row) * K + k0 + seg * 8);
            cp16(buf + 128 * 144 + row * 144 + seg * 16,
                 W + (size_t)(bn + row) * K + k0 + seg * 8);
        }
        asm volatile("cp.async.commit_group;" ::: "memory");
    };

    const int nch = K >> 6;
    prefetch(0);
    for (int c = 0; c < nch; c++) {
        if (c + 1 < nch) {
            prefetch(c + 1);
            asm volatile("cp.async.wait_group 1;" ::: "memory");
        } else {
            asm volatile("cp.async.wait_group 0;" ::: "memory");
        }
        __syncthreads();
        const uint32_t As = sbase + (c & 1) * HG_BUF;
        const uint32_t Bs = As + 128 * 144;
        #pragma unroll
        for (int kk = 0; kk < 4; kk++) {
            const uint32_t kb = (uint32_t)(kk * 32);
            uint32_t af[4][4];
            #pragma unroll
            for (int mi = 0; mi < 4; mi++)
                ldsm4(af[mi], As + (a_row + mi * 16) * 144 + a_sel + kb);
            #pragma unroll
            for (int njp = 0; njp < 4; njp++) {
                uint32_t bf[4];
                ldsm4(bf, Bs + (b_row + njp * 16) * 144 + b_sel + kb);
                #pragma unroll
                for (int mi = 0; mi < 4; mi++) {
                    mma_f16(acc[mi][njp * 2],     af[mi], bf[0], bf[1]);
                    mma_f16(acc[mi][njp * 2 + 1], af[mi], bf[2], bf[3]);
                }
            }
        }
        __syncthreads();
    }

    // epilogue: thread owns rows (r0, r0+8), cols (cc, cc+1) per (mi,nj)
    #pragma unroll
    for (int mi = 0; mi < 4; mi++) {
        const int r0 = bm + wm + mi * 16 + gid;
        #pragma unroll
        for (int nj = 0; nj < 8; nj++) {
            const int cc = bn + wn + nj * 8 + tig * 2;
            if (cc >= N) continue;           // N even, cc even -> cc+1 < N too
            const float bs0 = bias[cc], bs1 = bias[cc + 1];
            float v0 = acc[mi][nj][0] + bs0;
            float v1 = acc[mi][nj][1] + bs1;
            float v2 = acc[mi][nj][2] + bs0;
            float v3 = acc[mi][nj][3] + bs1;
            if (EPI == 1) {
                v0 = 0.5f * v0 * (1.f + erff(v0 * 0.70710678118654752f));
                v1 = 0.5f * v1 * (1.f + erff(v1 * 0.70710678118654752f));
                v2 = 0.5f * v2 * (1.f + erff(v2 * 0.70710678118654752f));
                v3 = 0.5f * v3 * (1.f + erff(v3 * 0.70710678118654752f));
            }
            if (EPI == 2) {
                float2 ra = *(const float2*)(res + (size_t)r0 * N + cc);
                float2 rb = *(const float2*)(res + (size_t)(r0 + 8) * N + cc);
                v0 += ra.x; v1 += ra.y; v2 += rb.x; v3 += rb.y;
            }
            st_out(C + (size_t)r0 * N + cc,           v0);
            st_out(C + (size_t)r0 * N + cc + 1,       v1);
            st_out(C + (size_t)(r0 + 8) * N + cc,     v2);
            st_out(C + (size_t)(r0 + 8) * N + cc + 1, v3);
        }
    }
}

// ---------------- transpose random-feature matrix once ----------------
__global__ void k_wrT(const float* __restrict__ w, float* __restrict__ wrT)
{
    int i = threadIdx.x + blockIdx.x * 256;
    if (i < 2048) { int e = i >> 5, m = i & 31; wrT[e * 32 + m] = w[m * 64 + e]; }
}

// ---------------- prm_exp for k and q (64 token-heads per block) ----------------
__global__ void __launch_bounds__(256)
k_prm(const float* __restrict__ kqv, const float* __restrict__ wrT,
      float* __restrict__ kp, float* __restrict__ qp)
{
    __shared__ float zs[64][65];
    __shared__ float ws[64][32];
    int tid = threadIdx.x;
    int th0 = blockIdx.x * 64;
    for (int i = tid; i < 2048; i += 256) ws[i >> 5][i & 31] = wrT[i];
    int w = tid >> 5, lane = tid & 31;
    int thb = w * 8;

    for (int kq = 0; kq < 2; kq++) {
        __syncthreads();
        for (int i = tid; i < 4096; i += 256) {
            int th = i >> 6, e = i & 63;
            zs[th][e] = kqv[(size_t)(th0 + th) * 192 + kq * 64 + e];
        }
        __syncthreads();
        float* out = kq ? qp : kp;
        float acc[8], xd[8];
        #pragma unroll
        for (int i = 0; i < 8; i++) {
            float z0 = zs[thb + i][lane], z1 = zs[thb + i][lane + 32];
            float p = z0 * z0 + z1 * z1;
            #pragma unroll
            for (int o = 16; o; o >>= 1) p += __shfl_xor_sync(0xffffffffu, p, o);
            xd[i] = 0.5f * p;
            acc[i] = 0.f;
        }
        #pragma unroll 4
        for (int e = 0; e < 64; e++) {
            float wvv = ws[e][lane];
            #pragma unroll
            for (int i = 0; i < 8; i++) acc[i] += zs[thb + i][e] * wvv;
        }
        #pragma unroll
        for (int i = 0; i < 8; i++)
            out[(size_t)(th0 + thb + i) * 32 + lane] = __expf(acc[i] - xd[i]) * INV_SQRT_M;
    }
}

// ---------------- kptv / ksum partial reduction over T chunks ----------------
__global__ void __launch_bounds__(256)
k_kptv_part(const float* __restrict__ kp, const float* __restrict__ kqv,
            float* __restrict__ kptv_p, float* __restrict__ ksum_p)
{
    int bh = blockIdx.x >> 4;
    int ch = blockIdx.x & 15;
    int b  = bh >> 3, h = bh & 7;
    int tid = threadIdx.x, eg = tid >> 5, lane = tid & 31;
    __shared__ float ks[8][32];
    __shared__ float vs[8][64];
    float acc[8] = {0, 0, 0, 0, 0, 0, 0, 0};
    float ksacc = 0.f;
    int tbase = ch * (T / NCH);
    for (int tt = 0; tt < T / NCH; tt += 8) {
        __syncthreads();
        {
            int tb = tid >> 5, m = tid & 31;
            int t = tbase + tt + tb;
            ks[tb][m] = kp[((size_t)((b * T + t) * Hh + h)) * 32 + m];
        }
        #pragma unroll
        for (int i = tid; i < 512; i += 256) {
            int tb = i >> 6, e = i & 63;
            int t = tbase + tt + tb;
            vs[tb][e] = kqv[(size_t)((b * T + t) * Hh + h) * 192 + 128 + e];
        }
        __syncthreads();
        #pragma unroll
        for (int tb = 0; tb < 8; tb++) {
            float kv = ks[tb][lane];
            if (eg == 0) ksacc += kv;
            #pragma unroll
            for (int j = 0; j < 8; j++) acc[j] += vs[tb][eg * 8 + j] * kv;
        }
    }
    size_t base = (size_t)blockIdx.x * 2048;
    #pragma unroll
    for (int j = 0; j < 8; j++) kptv_p[base + (eg * 8 + j) * 32 + lane] = acc[j];
    if (tid < 32) ksum_p[blockIdx.x * 32 + tid] = ksacc;
}

__global__ void __launch_bounds__(256)
k_kptv_red(const float* __restrict__ p, const float* __restrict__ ksp,
           float* __restrict__ kptvT, float* __restrict__ ksum)
{
    int bh = blockIdx.x, tid = threadIdx.x;
    for (int i = tid; i < 2048; i += 256) {
        float s = 0.f;
        #pragma unroll
        for (int c = 0; c < NCH; c++) s += p[((size_t)bh * NCH + c) * 2048 + i];
        int e = i >> 5, m = i & 31;
        kptvT[(size_t)bh * 2048 + m * 64 + e] = s;  // transposed [m][e]
    }
    if (tid < 32) {
        float s = 0.f;
        #pragma unroll
        for (int c = 0; c < NCH; c++) s += ksp[(bh * NCH + c) * 32 + tid];
        ksum[bh * 32 + tid] = s;
    }
}

// ---------------- y = (qp @ kptv^T) / D   (32 tokens x 2 heads per block; half out) ----
__global__ void __launch_bounds__(256)
k_y(const float* __restrict__ qp, const float* __restrict__ kptvT,
    const float* __restrict__ ksum, __half* __restrict__ y)
{
    __shared__ float kpt[2][2048];
    __shared__ float qps[64][33];
    __shared__ float kss[2][32];
    __shared__ float Ds[64];
    int tid = threadIdx.x;
    int hp = blockIdx.x & 3, h0 = hp * 2;
    int tok0 = (blockIdx.x >> 2) * 32;
    int b = tok0 >> 12;
    size_t kbase = (size_t)(b * 8 + h0) * 2048;
    for (int i = tid; i < 4096; i += 256) kpt[i >> 11][i & 2047] = kptvT[kbase + i];
    if (tid < 64) kss[tid >> 5][tid & 31] = ksum[(b * 8 + h0) * 32 + tid];
    for (int j = tid; j < 2048; j += 256) {
        int t = j >> 6, r = j & 63, hh = r >> 5, m = r & 31;
        qps[t * 2 + hh][m] = qp[(size_t)(tok0 + t) * 256 + (h0 + hh) * 32 + m];
    }
    __syncthreads();
    if (tid < 64) {
        int t = tid >> 1, hh = tid & 1;
        float s = 0.f;
        #pragma unroll
        for (int m = 0; m < 32; m++) s += qps[t * 2 + hh][m] * kss[hh][m];
        Ds[tid] = s;
    }
    __syncthreads();
    int w = tid >> 5, lane = tid & 31;
    int hh = w & 1, gg = w >> 1;
    float a0[8] = {0,0,0,0,0,0,0,0}, a1[8] = {0,0,0,0,0,0,0,0};
    #pragma unroll 4
    for (int m = 0; m < 32; m++) {
        float k0 = kpt[hh][m * 64 + lane];
        float k1 = kpt[hh][m * 64 + lane + 32];
        #pragma unroll
        for (int t = 0; t < 8; t++) {
            float qv = qps[(gg * 8 + t) * 2 + hh][m];
            a0[t] += qv * k0; a1[t] += qv * k1;
        }
    }
    #pragma unroll
    for (int t = 0; t < 8; t++) {
        int tok = tok0 + gg * 8 + t;
        float inv = 1.0f / Ds[(gg * 8 + t) * 2 + hh];
        y[(size_t)tok * 512 + (h0 + hh) * 64 + lane]      = __float2half_rn(a0[t] * inv);
        y[(size_t)tok * 512 + (h0 + hh) * 64 + lane + 32] = __float2half_rn(a1[t] * inv);
    }
}

// ---------------- launcher ----------------
extern "C" void kernel_launch(void* const* d_in, const int* in_sizes, int n_in,
                              void* d_out, int out_size)
{
    (void)in_sizes; (void)n_in; (void)out_size;
    const float* x      = (const float*)d_in[0];
    const float* w_rf   = (const float*)d_in[1];
    const float* kqv_w  = (const float*)d_in[2];
    const float* kqv_b  = (const float*)d_in[3];
    const float* proj_w = (const float*)d_in[4];
    const float* proj_b = (const float*)d_in[5];
    const float* ln1_g  = (const float*)d_in[6];
    const float* ln1_b  = (const float*)d_in[7];
    const float* ln2_g  = (const float*)d_in[8];
    const float* ln2_b  = (const float*)d_in[9];
    const float* w1     = (const float*)d_in[10];
    const float* b1     = (const float*)d_in[11];
    const float* w2     = (const float*)d_in[12];
    const float* b2     = (const float*)d_in[13];
    float* out = (float*)d_out;

    float* scr = nullptr;
    cudaGetSymbolAddress((void**)&scr, g_scr);
    __half* dhh    = (__half*)(scr + OFF_H);
    float*  dkqv   = scr + OFF_KQV;
    float*  dkp    = scr + OFF_KP;
    float*  dqp    = scr + OFF_QP;
    float*  dwrT   = scr + OFF_WRT;
    float*  dkptvp = scr + OFF_KPTV_P;
    float*  dksump = scr + OFF_KSUM_P;
    float*  dkptvT = scr + OFF_KPTVT;
    float*  dksum  = scr + OFF_KSUM;
    float*  dx2    = scr + OFF_X2;
    __half* dyh    = (__half*)(scr + OFF_YH);
    __half* dh2h   = (__half*)(scr + OFF_H2H);
    __half* dhidh  = (__half*)(scr + OFF_HIDH);
    __half* dpwh   = (__half*)(scr + OFF_PWH);
    __half* dw1h   = (__half*)(scr + OFF_W1H);
    __half* dw2h   = (__half*)(scr + OFF_W2H);
    __half* dkwh   = (__half*)(scr + OFF_KWH);

    cudaFuncSetAttribute(k_hgemm<0, float>,  cudaFuncAttributeMaxDynamicSharedMemorySize, HG_SMEM);
    cudaFuncSetAttribute(k_hgemm<1, __half>, cudaFuncAttributeMaxDynamicSharedMemorySize, HG_SMEM);
    cudaFuncSetAttribute(k_hgemm<2, float>,  cudaFuncAttributeMaxDynamicSharedMemorySize, HG_SMEM);

    // 0. weight conversions (independent)
    k_f2h<<<512 * 512 / 1024, 256>>>(proj_w, dpwh);
    k_f2h<<<2048 * 512 / 1024, 256>>>(w1, dw1h);
    k_f2h<<<512 * 2048 / 1024, 256>>>(w2, dw2h);
    k_f2h_pad<<<64, 256>>>(kqv_w, dkwh, 192 * 64, 256 * 64);
    // 1. LN1 (half out — feeds fp16 kqv GEMM)
    k_layernorm<__half><<<NTOK, 256>>>(x, ln1_g, ln1_b, dhh);
    // 2. kqv = h @ kqv_w^T + b (fp16 tensor cores, fp32 out; W padded to 256 rows)
    k_hgemm<0, float><<<dim3(2, NTH / 128), 128, HG_SMEM>>>(dhh, dkwh, kqv_b, nullptr, dkqv, 192, 64);
    // 3. random features
    k_wrT<<<8, 256>>>(w_rf, dwrT);
    k_prm<<<NTH / 64, 256>>>(dkqv, dwrT, dkp, dqp);
    // 4. kptv / ksum reduction over T
    k_kptv_part<<<64 * NCH, 256>>>(dkp, dkqv, dkptvp, dksump);
    k_kptv_red<<<64, 256>>>(dkptvp, dksump, dkptvT, dksum);
    // 5. y (half out)
    k_y<<<(NTOK / 32) * 4, 256>>>(dqp, dkptvT, dksum, dyh);
    // 6. attn proj + residual -> x2 (fp16 tensor cores)
    k_hgemm<2, float><<<dim3(4, NTOK / 128), 128, HG_SMEM>>>(dyh, dpwh, proj_b, x, dx2, 512, 512);
    // 7. LN2 (half out)
    k_layernorm<__half><<<NTOK, 256>>>(dx2, ln2_g, ln2_b, dh2h);
    // 8. MLP (fp16 tensor cores)
    k_hgemm<1, __half><<<dim3(16, NTOK / 128), 128, HG_SMEM>>>(dh2h, dw1h, b1, nullptr, dhidh, 2048, 512);
    k_hgemm<2, float><<<dim3(4, NTOK / 128), 128, HG_SMEM>>>(dhidh, dw2h, b2, dx2, out, 512, 2048);
}